// round 15
// baseline (speedup 1.0000x reference)
#include <cuda_runtime.h>
#include <cuda_bf16.h>
#include <math_constants.h>

#define NEDGE 320000
#define NATOM 10000
#define HID   128
#define CUT   5.0f
#define NTAB  8192

typedef unsigned long long u64;
typedef unsigned int u32;

// ---------------- scratch (static device memory; no allocations) ----------------
__device__ __align__(16) float g_m   [(size_t)NEDGE * HID];   // m buffer 0
__device__ __align__(16) float g_m2  [(size_t)NEDGE * HID];   // m buffer 1
__device__ __align__(16) float g_ang4[(size_t)4 * NEDGE];
__device__ __align__(16) float g_h   [(size_t)NATOM * HID];
__device__ __align__(16) float g_agg [4][(size_t)NATOM * HID];
__device__ __align__(16) float g_tabrbf[(size_t)NTAB * 16];
__device__ __align__(16) float g_tabs[(size_t)9 * NTAB * HID];  // 0..4 ob, 5..8 ib
__device__ __align__(16) float g_tabm[(size_t)NTAB * HID];
__device__ __align__(16) __nv_bfloat16 g_wbh[(size_t)9 * HID * HID];
__device__ __align__(16) __nv_bfloat16 g_wbl[(size_t)9 * HID * HID];
__device__ int g_csr_cnt [NATOM];
__device__ int g_csr_pos [NATOM];
__device__ int g_csr_off [NATOM + 1];
__device__ int g_csr_edge[NEDGE];

__device__ __forceinline__ float silu_f(float x) { return x / (1.0f + __expf(-x)); }

__device__ __forceinline__ void red_add_v4(float* p, float4 v)
{
    asm volatile("red.global.add.v4.f32 [%0], {%1,%2,%3,%4};"
                 :: "l"(p), "f"(v.x), "f"(v.y), "f"(v.z), "f"(v.w) : "memory");
}

// ---------------- packed f32x2 helpers ----------------
__device__ __forceinline__ u64 pack2(float a) {
    u64 r; asm("mov.b64 %0, {%1, %1};" : "=l"(r) : "f"(a)); return r;
}
__device__ __forceinline__ void fma2(u64& d, u64 a, u64 b) {
    asm("fma.rn.f32x2 %0, %1, %2, %3;" : "=l"(d) : "l"(a), "l"(b), "l"(d));
}
__device__ __forceinline__ float2 unpack2(u64 v) {
    float2 f; asm("mov.b64 {%0, %1}, %2;" : "=f"(f.x), "=f"(f.y) : "l"(v)); return f;
}

// ---------------- bessel rbf ----------------
__device__ __forceinline__ void rbf_eval(float d, float* out16)
{
    float x = d * (1.0f / CUT);
    float x2 = x * x;
    float x6 = x2 * x2 * x2;
    float x7 = x6 * x;
    float x8 = x7 * x;
    float env = 1.0f - 28.0f * x6 + 48.0f * x7 - 21.0f * x8;
    if (!(d < CUT)) env = 0.0f;
    float s = sqrtf(2.0f / CUT) / d * env;
    float base = (float)CUDART_PI_F / CUT * d;
#pragma unroll
    for (int k = 0; k < 16; k++)
        out16[k] = s * sinf(base * (float)(k + 1));
}

__global__ void tab_prep_kernel()
{
    int i = blockIdx.x * blockDim.x + threadIdx.x;
    if (i >= NTAB) return;
    float d = fmaxf((float)i * (CUT / (float)(NTAB - 1)), 1e-4f);
    float r16[16];
    rbf_eval(d, r16);
#pragma unroll
    for (int k = 0; k < 16; k++) g_tabrbf[(size_t)i * 16 + k] = r16[k];
}

__device__ __forceinline__ float4 tab_lerp_t(const float* tab, float d, int lane)
{
    float t = d * ((float)(NTAB - 1) / CUT);
    int i0 = min((int)t, NTAB - 2);
    float f = t - (float)i0;
    float4 lo = ((const float4*)(tab + (size_t)i0 * HID))[lane];
    float4 hi = ((const float4*)(tab + (size_t)(i0 + 1) * HID))[lane];
    float4 o;
    o.x = lo.x + (hi.x - lo.x) * f;
    o.y = lo.y + (hi.y - lo.y) * f;
    o.z = lo.z + (hi.z - lo.z) * f;
    o.w = lo.w + (hi.w - lo.w) * f;
    return o;
}

// scalar float2 lerp at (d, col): used by fused phase 3 when m comes from the table
__device__ __forceinline__ float2 tab_lerp2(const float* tab, float d, int col)
{
    float t = d * ((float)(NTAB - 1) / CUT);
    int i0 = min((int)t, NTAB - 2);
    float f = t - (float)i0;
    float2 lo = *(const float2*)(tab + (size_t)i0 * HID + col);
    float2 hi = *(const float2*)(tab + (size_t)(i0 + 1) * HID + col);
    return make_float2(lo.x + (hi.x - lo.x) * f, lo.y + (hi.y - lo.y) * f);
}

// ---------------- CSR build ----------------
__global__ void csr_count_kernel(const int* __restrict__ ei)
{
    int e = blockIdx.x * blockDim.x + threadIdx.x;
    if (e >= NEDGE) return;
    atomicAdd(&g_csr_cnt[ei[NEDGE + e]], 1);
}

__global__ void csr_scan_kernel()
{
    __shared__ int part[1024];
    const int tid = threadIdx.x;
    const int base = tid * 10;
    int s = 0;
#pragma unroll
    for (int k = 0; k < 10; k++) {
        int idx = base + k;
        if (idx < NATOM) s += g_csr_cnt[idx];
    }
    part[tid] = s;
    __syncthreads();
    for (int off = 1; off < 1024; off <<= 1) {
        int v = 0;
        if (tid >= off) v = part[tid - off];
        __syncthreads();
        part[tid] += v;
        __syncthreads();
    }
    int run = part[tid] - s;
#pragma unroll
    for (int k = 0; k < 10; k++) {
        int idx = base + k;
        if (idx < NATOM) {
            g_csr_off[idx] = run;
            run += g_csr_cnt[idx];
        }
    }
    if (tid == 1023) g_csr_off[NATOM] = run;
}

__global__ void csr_fill_kernel(const int* __restrict__ ei)
{
    int e = blockIdx.x * blockDim.x + threadIdx.x;
    if (e >= NEDGE) return;
    int dd = ei[NEDGE + e];
    int p = atomicAdd(&g_csr_pos[dd], 1);
    g_csr_edge[g_csr_off[dd] + p] = e;
}

// ---------------- m table ----------------
__global__ void tabm_kernel(const float* __restrict__ embed_w, const float* __restrict__ embed_b)
{
    __shared__ float Ws[16 * 128];
    __shared__ float bs[128];
    __shared__ float rs[8 * 16];
    int tid = threadIdx.x;
    for (int i = tid; i < 2048; i += 256)
        Ws[i] = embed_w[(i >> 7) * 384 + 256 + (i & 127)];
    if (tid < 128) bs[tid] = embed_b[256 + tid];
    int e0 = blockIdx.x * 8;
    if (tid < 128) rs[tid] = g_tabrbf[(size_t)e0 * 16 + tid];
    __syncthreads();
    int w = tid >> 5, lane = tid & 31;
    int e = e0 + w;
    float4 acc = *(const float4*)&bs[lane * 4];
#pragma unroll
    for (int k = 0; k < 16; k++) {
        float a = rs[w * 16 + k];
        float4 wv = *(const float4*)&Ws[k * 128 + lane * 4];
        acc.x += a * wv.x; acc.y += a * wv.y; acc.z += a * wv.z; acc.w += a * wv.w;
    }
    ((float4*)(g_tabm + (size_t)e * HID))[lane] = acc;
}

// ---------------- pre-split ib_out_w ----------------
__global__ void wsplit_kernel(const float* __restrict__ W)
{
    int i = blockIdx.x * blockDim.x + threadIdx.x;
    if (i >= 9 * HID * HID) return;
    int mat = i >> 14;
    int r = i & 16383;
    int k = r >> 7, n = r & 127;
    float w = W[i];
    __nv_bfloat16 h = __float2bfloat16(w);
    float rr = w - __bfloat162float(h);
    size_t o = (size_t)mat * 16384 + n * 128 + k;
    g_wbh[o] = h;
    g_wbl[o] = __float2bfloat16(rr);
}

__global__ void h_init_kernel(const int* __restrict__ Z, const float* __restrict__ emb)
{
    int idx = blockIdx.x * blockDim.x + threadIdx.x;
    int a = idx >> 5, lane = idx & 31;
    if (a >= NATOM) return;
    int z = Z[a] - 1;
    ((float4*)(g_h + (size_t)a * HID))[lane] =
        ((const float4*)(emb + (size_t)z * HID))[lane];
}

// ---------------- batched angle ----------------
__global__ void angle_batch_kernel(const float* __restrict__ sphW, const float* __restrict__ sphB,
                                   const float* __restrict__ dirs)
{
    __shared__ float wbar[8];
    __shared__ float bbar;
    const int inst = blockIdx.y;
    const float* W = sphW + inst * 56;
    const float* B = sphB + inst * 8;
    if (threadIdx.x < 7) {
        float s = 0.0f;
#pragma unroll
        for (int j = 0; j < 8; j++) s += W[threadIdx.x * 8 + j];
        wbar[threadIdx.x] = s * 0.125f;
    }
    if (threadIdx.x == 7) {
        float s = 0.0f;
#pragma unroll
        for (int j = 0; j < 8; j++) s += B[j];
        bbar = s * 0.125f;
    }
    __syncthreads();
    int e = blockIdx.x * blockDim.x + threadIdx.x;
    if (e >= NEDGE) return;
    float dx = dirs[e * 3 + 0], dy = dirs[e * 3 + 1], dz = dirs[e * 3 + 2];
    float acc = bbar + wbar[0] + wbar[1] * dy + wbar[2] * dz + wbar[3] * dx
              + wbar[4] * dx * dy + wbar[5] * dy * dz + wbar[6] * (3.0f * dz * dz - 1.0f);
    g_ang4[(size_t)inst * NEDGE + e] = 1.0f / (1.0f + __expf(-acc));
}

// ---------------- SIMT GEMM core ----------------
__device__ __forceinline__ void gemm_core8(const float* __restrict__ Ws,
                                           const float* __restrict__ Xs,
                                           u64 acc[4][4], int tx, int ty)
{
#pragma unroll 2
    for (int k0 = 0; k0 < 128; k0 += 4) {
        float4 av[4];
#pragma unroll
        for (int r = 0; r < 4; r++)
            av[r] = *(const float4*)(Xs + (ty * 4 + r) * 128 + k0);
#pragma unroll
        for (int kk = 0; kk < 4; kk++) {
            ulonglong2 b01 = *(const ulonglong2*)(Ws + (k0 + kk) * 128 + tx * 8);
            ulonglong2 b23 = *(const ulonglong2*)(Ws + (k0 + kk) * 128 + tx * 8 + 4);
#pragma unroll
            for (int r = 0; r < 4; r++) {
                float aval = ((const float*)&av[r])[kk];
                u64 ap = pack2(aval);
                fma2(acc[r][0], ap, b01.x);
                fma2(acc[r][1], ap, b01.y);
                fma2(acc[r][2], ap, b23.x);
                fma2(acc[r][3], ap, b23.y);
            }
        }
    }
}

// ---------------- batched radial MLP ----------------
#define RAD_SMEM ((16384 + 8192 + 2048 + 128 + 1024) * 4)
__global__ void __launch_bounds__(256, 2) rad_mlp_batch_kernel(
    const float* __restrict__ ob_w1, const float* __restrict__ ob_b1,
    const float* __restrict__ ob_w2, const float* __restrict__ ob_b2,
    const float* __restrict__ ib_w1, const float* __restrict__ ib_b1,
    const float* __restrict__ ib_w2, const float* __restrict__ ib_b2)
{
    extern __shared__ float sm[];
    float* W2s = sm;
    float* Hs  = sm + 16384;
    float* W1s = sm + 16384 + 8192;
    float* b1s = W1s + 2048;
    float* Rs  = b1s + 128;
    const int tid = threadIdx.x;
    const int row0 = blockIdx.x * 64;
    const int inst = blockIdx.y;
    const float *rW1, *rb1, *rW2, *rb2;
    if (inst < 5) {
        rW1 = ob_w1 + (size_t)inst * 2048;  rb1 = ob_b1 + inst * 128;
        rW2 = ob_w2 + (size_t)inst * 16384; rb2 = ob_b2 + inst * 128;
    } else {
        int i = inst - 5;
        rW1 = ib_w1 + (size_t)i * 2048;  rb1 = ib_b1 + i * 128;
        rW2 = ib_w2 + (size_t)i * 16384; rb2 = ib_b2 + i * 128;
    }
    float* Y = g_tabs + (size_t)inst * NTAB * HID;

    for (int i = tid; i < 4096; i += 256) ((float4*)W2s)[i] = ((const float4*)rW2)[i];
    for (int i = tid; i < 512;  i += 256) ((float4*)W1s)[i] = ((const float4*)rW1)[i];
    if (tid < 32) ((float4*)b1s)[tid] = ((const float4*)rb1)[tid];
    {
        int r = tid >> 2;
        ((float4*)Rs)[tid] = ((const float4*)(g_tabrbf + (size_t)(row0 + r) * 16))[tid & 3];
    }
    __syncthreads();
    {
        const int tx5 = tid & 31, ty5 = tid >> 5;
        float4 b1v = *(const float4*)&b1s[tx5 * 4];
#pragma unroll
        for (int i = 0; i < 8; i++) {
            int r = ty5 * 8 + i;
            float4 a4 = b1v;
#pragma unroll
            for (int k = 0; k < 16; k++) {
                float a = Rs[r * 16 + k];
                float4 w = *(const float4*)&W1s[k * 128 + tx5 * 4];
                a4.x += a * w.x; a4.y += a * w.y; a4.z += a * w.z; a4.w += a * w.w;
            }
            a4.x = silu_f(a4.x); a4.y = silu_f(a4.y); a4.z = silu_f(a4.z); a4.w = silu_f(a4.w);
            *(float4*)&Hs[r * 128 + tx5 * 4] = a4;
        }
    }
    __syncthreads();
    const int tx = tid & 15, ty = tid >> 4;
    u64 acc[4][4];
#pragma unroll
    for (int r = 0; r < 4; r++)
#pragma unroll
        for (int c = 0; c < 4; c++) acc[r][c] = 0ull;
    gemm_core8(W2s, Hs, acc, tx, ty);
    float4 blo = *(const float4*)(rb2 + tx * 8);
    float4 bhi = *(const float4*)(rb2 + tx * 8 + 4);
#pragma unroll
    for (int r = 0; r < 4; r++) {
        int row = ty * 4 + r;
        float2 p0 = unpack2(acc[r][0]);
        float2 p1 = unpack2(acc[r][1]);
        float2 p2 = unpack2(acc[r][2]);
        float2 p3 = unpack2(acc[r][3]);
        float* yp = Y + (size_t)(row0 + row) * 128 + tx * 8;
        *(float4*)yp       = make_float4(p0.x + blo.x, p0.y + blo.y, p1.x + blo.z, p1.y + blo.w);
        *(float4*)(yp + 4) = make_float4(p2.x + bhi.x, p2.y + bhi.y, p3.x + bhi.z, p3.y + bhi.w);
    }
}

// ---------------- fused h update ----------------
#define HUPD_SMEM ((16384 + 8192) * 4)
__global__ void __launch_bounds__(256, 2) hupdate_kernel(const float* __restrict__ agg,
                                                         const float* __restrict__ w1,
                                                         const float* __restrict__ b1,
                                                         const float* __restrict__ w2,
                                                         const float* __restrict__ b2,
                                                         int nrows)
{
    extern __shared__ float sm[];
    float* Ws = sm;
    float* Xs = sm + 16384;
    const int tid = threadIdx.x;
    const int row0 = blockIdx.x * 64;
    const int rows = min(64, nrows - row0);
    const int tx = tid & 15, ty = tid >> 4;

    for (int i = tid; i < 2048; i += 256) {
        int r = i >> 5, c = i & 31;
        float4 v = make_float4(0.f, 0.f, 0.f, 0.f);
        if (r < rows) v = ((const float4*)(g_h + (size_t)(row0 + r) * 128))[c];
        ((float4*)Xs)[i] = v;
    }
    for (int i = tid; i < 4096; i += 256) ((float4*)Ws)[i] = ((const float4*)w1)[i];
    __syncthreads();
    u64 acc[4][4];
#pragma unroll
    for (int r = 0; r < 4; r++)
#pragma unroll
        for (int c = 0; c < 4; c++) acc[r][c] = 0ull;
    gemm_core8(Ws, Xs, acc, tx, ty);
    __syncthreads();

    for (int i = tid; i < 2048; i += 256) {
        int r = i >> 5, c = i & 31;
        float4 v = make_float4(0.f, 0.f, 0.f, 0.f);
        if (r < rows) v = ((const float4*)(agg + (size_t)(row0 + r) * 128))[c];
        ((float4*)Xs)[i] = v;
    }
    for (int i = tid; i < 4096; i += 256) ((float4*)Ws)[i] = ((const float4*)(w1 + 16384))[i];
    __syncthreads();
    gemm_core8(Ws, Xs, acc, tx, ty);
    __syncthreads();

    {
        float4 blo = *(const float4*)(b1 + tx * 8);
        float4 bhi = *(const float4*)(b1 + tx * 8 + 4);
#pragma unroll
        for (int r = 0; r < 4; r++) {
            int row = ty * 4 + r;
            float2 p0 = unpack2(acc[r][0]);
            float2 p1 = unpack2(acc[r][1]);
            float2 p2 = unpack2(acc[r][2]);
            float2 p3 = unpack2(acc[r][3]);
            *(float4*)&Xs[row * 128 + tx * 8] =
                make_float4(silu_f(p0.x + blo.x), silu_f(p0.y + blo.y),
                            silu_f(p1.x + blo.z), silu_f(p1.y + blo.w));
            *(float4*)&Xs[row * 128 + tx * 8 + 4] =
                make_float4(silu_f(p2.x + bhi.x), silu_f(p2.y + bhi.y),
                            silu_f(p3.x + bhi.z), silu_f(p3.y + bhi.w));
        }
    }
    for (int i = tid; i < 4096; i += 256) ((float4*)Ws)[i] = ((const float4*)w2)[i];
    __syncthreads();

#pragma unroll
    for (int r = 0; r < 4; r++)
#pragma unroll
        for (int c = 0; c < 4; c++) acc[r][c] = 0ull;
    gemm_core8(Ws, Xs, acc, tx, ty);
    {
        float4 blo = *(const float4*)(b2 + tx * 8);
        float4 bhi = *(const float4*)(b2 + tx * 8 + 4);
#pragma unroll
        for (int r = 0; r < 4; r++) {
            int row = ty * 4 + r;
            if (row >= rows) break;
            float2 p0 = unpack2(acc[r][0]);
            float2 p1 = unpack2(acc[r][1]);
            float2 p2 = unpack2(acc[r][2]);
            float2 p3 = unpack2(acc[r][3]);
            float* hp = g_h + (size_t)(row0 + row) * 128 + tx * 8;
            float4 u0 = *(float4*)hp;
            float4 u1 = *(float4*)(hp + 4);
            u0.x += p0.x + blo.x; u0.y += p0.y + blo.y; u0.z += p1.x + blo.z; u0.w += p1.y + blo.w;
            u1.x += p2.x + bhi.x; u1.y += p2.y + bhi.y; u1.z += p3.x + bhi.z; u1.w += p3.y + bhi.w;
            *(float4*)hp = u0;
            *(float4*)(hp + 4) = u1;
        }
    }
}

// ---------------- fused scatter + output block ----------------
// Builds Xs directly from the CSR scatter (x[a] = sum h[src]*radf), then 3 dense layers + proj.
#define OUT_SMEM ((16384 + 8192 + 128) * 4)
template<bool ACCUM>
__global__ void __launch_bounds__(256, 2) outblock_kernel(const int* __restrict__ ei,
                                                          const float* __restrict__ dist,
                                                          const float* __restrict__ tab,
                                                          const float* __restrict__ dw,
                                                          const float* __restrict__ db,
                                                          const float* __restrict__ ow,
                                                          const float* __restrict__ obias,
                                                          float* __restrict__ out, int nrows)
{
    extern __shared__ float sm[];
    float* Ws   = sm;
    float* Xs   = sm + 16384;
    float* wout = sm + 16384 + 8192;
    const int tid = threadIdx.x;
    const int row0 = blockIdx.x * 64;
    const int rows = min(64, nrows - row0);
    const int tx = tid & 15, ty = tid >> 4;
    const int wid = tid >> 5, lane = tid & 31;

    if (tid < 32) ((float4*)wout)[tid] = ((const float4*)ow)[tid];

    // CSR scatter into Xs: 8 warps x 8 atoms
#pragma unroll
    for (int a8 = 0; a8 < 8; a8++) {
        int rloc = wid * 8 + a8;
        int a = row0 + rloc;
        float4 acc = make_float4(0.f, 0.f, 0.f, 0.f);
        if (a < nrows) {
            int b0 = g_csr_off[a], b1 = g_csr_off[a + 1];
            for (int idx = b0; idx < b1; idx++) {
                int e = g_csr_edge[idx];
                int s = ei[e];
                float4 hv = ((const float4*)(g_h + (size_t)s * HID))[lane];
                float4 wv = tab_lerp_t(tab, dist[e], lane);
                acc.x += hv.x * wv.x;
                acc.y += hv.y * wv.y;
                acc.z += hv.z * wv.z;
                acc.w += hv.w * wv.w;
            }
        }
        *(float4*)&Xs[rloc * 128 + lane * 4] = acc;
    }

    for (int j = 0; j < 3; j++) {
        __syncthreads();
        for (int i = tid; i < 4096; i += 256)
            ((float4*)Ws)[i] = ((const float4*)(dw + (size_t)j * 16384))[i];
        __syncthreads();
        u64 acc[4][4];
#pragma unroll
        for (int r = 0; r < 4; r++)
#pragma unroll
            for (int c = 0; c < 4; c++) acc[r][c] = 0ull;
        gemm_core8(Ws, Xs, acc, tx, ty);
        __syncthreads();
        float4 blo = *(const float4*)(db + j * 128 + tx * 8);
        float4 bhi = *(const float4*)(db + j * 128 + tx * 8 + 4);
#pragma unroll
        for (int r = 0; r < 4; r++) {
            int row = ty * 4 + r;
            float2 p0 = unpack2(acc[r][0]);
            float2 p1 = unpack2(acc[r][1]);
            float2 p2 = unpack2(acc[r][2]);
            float2 p3 = unpack2(acc[r][3]);
            *(float4*)&Xs[row * 128 + tx * 8] =
                make_float4(silu_f(p0.x + blo.x), silu_f(p0.y + blo.y),
                            silu_f(p1.x + blo.z), silu_f(p1.y + blo.w));
            *(float4*)&Xs[row * 128 + tx * 8 + 4] =
                make_float4(silu_f(p2.x + bhi.x), silu_f(p2.y + bhi.y),
                            silu_f(p3.x + bhi.z), silu_f(p3.y + bhi.w));
        }
    }
    __syncthreads();

    float bias0 = obias[0];
    float4 wv = *(const float4*)&wout[lane * 4];
#pragma unroll
    for (int r8 = 0; r8 < 8; r8++) {
        int row = wid * 8 + r8;
        float4 xv = *(const float4*)&Xs[row * 128 + lane * 4];
        float s = xv.x * wv.x + xv.y * wv.y + xv.z * wv.z + xv.w * wv.w;
#pragma unroll
        for (int off = 16; off > 0; off >>= 1) s += __shfl_xor_sync(0xFFFFFFFFu, s, off);
        if (lane == 0 && row < rows) {
            float v = s + bias0;
            if (ACCUM) out[row0 + row] += v; else out[row0 + row] = v;
        }
    }
}

// ---------------- FUSED triplet + bf16-split tensor GEMM x3 + m update (512 threads) ----------------
// M_FROM_TAB: first interaction block — m_old is the pure distance table (tabm), never materialized.
#define FUSED_SMEM (4 * 128 * 136 * 2)
__device__ __forceinline__ void mma_bf16(float* c, const u32* a, const u32* b)
{
    asm volatile("mma.sync.aligned.m16n8k16.row.col.f32.bf16.bf16.f32 "
                 "{%0,%1,%2,%3}, {%4,%5,%6,%7}, {%8,%9}, {%0,%1,%2,%3};"
                 : "+f"(c[0]), "+f"(c[1]), "+f"(c[2]), "+f"(c[3])
                 : "r"(a[0]), "r"(a[1]), "r"(a[2]), "r"(a[3]), "r"(b[0]), "r"(b[1]));
}

template<bool M_FROM_TAB>
__global__ void __launch_bounds__(512, 1) fused_trip_mma_kernel(
    const int* __restrict__ trip, const int* __restrict__ ei, const float* __restrict__ dist,
    const float* __restrict__ ang, const float* __restrict__ tab,
    const float* __restrict__ m_old, float* __restrict__ m_new, float* __restrict__ agg,
    const __nv_bfloat16* __restrict__ Wh3, const __nv_bfloat16* __restrict__ Wl3,
    const float* __restrict__ bias3)
{
    extern __shared__ __nv_bfloat16 smb[];
    __nv_bfloat16* sAh = smb;                 // [128][136]
    __nv_bfloat16* sAl = smb + 128 * 136;
    __nv_bfloat16* sBh = smb + 2 * 128 * 136;
    __nv_bfloat16* sBl = smb + 3 * 128 * 136;
    const int tid = threadIdx.x;
    const int row0 = blockIdx.x * 128;
    const int lane = tid & 31, wid = tid >> 5;   // 16 warps

    // ---- phase 1: triplet gather (8 rows per warp) ----
#pragma unroll 4
    for (int rr = 0; rr < 8; rr++) {
        int r = wid * 8 + rr;
        int gw = row0 + r;
        int ji = trip[gw * 3 + 0];
        int kj = trip[gw * 3 + 1];
        float aw = ang[ji];
        float dkj = dist[kj];
        float4 mv;
        if (M_FROM_TAB) mv = tab_lerp_t(g_tabm, dkj, lane);
        else            mv = ((const float4*)(m_old + (size_t)kj * HID))[lane];
        float4 rv = tab_lerp_t(tab, dkj, lane);
        float4 o = make_float4(mv.x * rv.x * aw, mv.y * rv.y * aw,
                               mv.z * rv.z * aw, mv.w * rv.w * aw);
        int dd = ei[NEDGE + gw];
        red_add_v4(agg + (size_t)dd * HID + lane * 4, o);

        __nv_bfloat162 h01, h23, l01, l23;
        h01.x = __float2bfloat16(o.x); h01.y = __float2bfloat16(o.y);
        h23.x = __float2bfloat16(o.z); h23.y = __float2bfloat16(o.w);
        l01.x = __float2bfloat16(o.x - __bfloat162float(h01.x));
        l01.y = __float2bfloat16(o.y - __bfloat162float(h01.y));
        l23.x = __float2bfloat16(o.z - __bfloat162float(h23.x));
        l23.y = __float2bfloat16(o.w - __bfloat162float(h23.y));
        *(__nv_bfloat162*)&sAh[r * 136 + lane * 4]     = h01;
        *(__nv_bfloat162*)&sAh[r * 136 + lane * 4 + 2] = h23;
        *(__nv_bfloat162*)&sAl[r * 136 + lane * 4]     = l01;
        *(__nv_bfloat162*)&sAl[r * 136 + lane * 4 + 2] = l23;
    }

    // ---- phase 2: 3 tensor GEMMs, warp grid 4x4 ----
    const int wm = wid >> 2, wn = wid & 3;
    const int gid = lane >> 2, tg = lane & 3;

    float msum[2][4][4];
#pragma unroll
    for (int a = 0; a < 2; a++)
#pragma unroll
        for (int b = 0; b < 4; b++)
#pragma unroll
            for (int c = 0; c < 4; c++) msum[a][b][c] = 0.0f;

    for (int j = 0; j < 3; j++) {
        __syncthreads();
        {
            const uint4* Wh4 = (const uint4*)(Wh3 + (size_t)j * 16384);
            const uint4* Wl4 = (const uint4*)(Wl3 + (size_t)j * 16384);
            for (int i = tid; i < 2048; i += 512) {
                int r = i >> 4, c = i & 15;
                *(uint4*)&sBh[r * 136 + c * 8] = Wh4[r * 16 + c];
                *(uint4*)&sBl[r * 136 + c * 8] = Wl4[r * 16 + c];
            }
        }
        __syncthreads();

        float acc[2][4][4];
#pragma unroll
        for (int a = 0; a < 2; a++)
#pragma unroll
            for (int b = 0; b < 4; b++)
#pragma unroll
                for (int c = 0; c < 4; c++) acc[a][b][c] = 0.0f;

#pragma unroll
        for (int ks = 0; ks < 8; ks++) {
            const int kb = ks * 16;
            u32 ah[2][4], al[2][4];
#pragma unroll
            for (int fm = 0; fm < 2; fm++) {
                int r = wm * 32 + fm * 16 + gid;
                ah[fm][0] = *(const u32*)&sAh[(r)     * 136 + kb + tg * 2];
                ah[fm][1] = *(const u32*)&sAh[(r + 8) * 136 + kb + tg * 2];
                ah[fm][2] = *(const u32*)&sAh[(r)     * 136 + kb + 8 + tg * 2];
                ah[fm][3] = *(const u32*)&sAh[(r + 8) * 136 + kb + 8 + tg * 2];
                al[fm][0] = *(const u32*)&sAl[(r)     * 136 + kb + tg * 2];
                al[fm][1] = *(const u32*)&sAl[(r + 8) * 136 + kb + tg * 2];
                al[fm][2] = *(const u32*)&sAl[(r)     * 136 + kb + 8 + tg * 2];
                al[fm][3] = *(const u32*)&sAl[(r + 8) * 136 + kb + 8 + tg * 2];
            }
            u32 bh[4][2], bl[4][2];
#pragma unroll
            for (int fn = 0; fn < 4; fn++) {
                int n = wn * 32 + fn * 8 + gid;
                bh[fn][0] = *(const u32*)&sBh[n * 136 + kb + tg * 2];
                bh[fn][1] = *(const u32*)&sBh[n * 136 + kb + 8 + tg * 2];
                bl[fn][0] = *(const u32*)&sBl[n * 136 + kb + tg * 2];
                bl[fn][1] = *(const u32*)&sBl[n * 136 + kb + 8 + tg * 2];
            }
#pragma unroll
            for (int fm = 0; fm < 2; fm++)
#pragma unroll
                for (int fn = 0; fn < 4; fn++) {
                    mma_bf16(acc[fm][fn], ah[fm], bh[fn]);
                    mma_bf16(acc[fm][fn], ah[fm], bl[fn]);
                    mma_bf16(acc[fm][fn], al[fm], bh[fn]);
                }
        }

        const float* bias = bias3 + j * 128;
#pragma unroll
        for (int fm = 0; fm < 2; fm++)
#pragma unroll
            for (int fn = 0; fn < 4; fn++) {
                int col = wn * 32 + fn * 8 + tg * 2;
                float2 b2 = *(const float2*)(bias + col);
                msum[fm][fn][0] += silu_f(acc[fm][fn][0] + b2.x);
                msum[fm][fn][1] += silu_f(acc[fm][fn][1] + b2.y);
                msum[fm][fn][2] += silu_f(acc[fm][fn][2] + b2.x);
                msum[fm][fn][3] += silu_f(acc[fm][fn][3] + b2.y);
            }
    }

    // ---- phase 3: m_new = m_old(base) + msum ----
#pragma unroll
    for (int fm = 0; fm < 2; fm++) {
        int row = row0 + wm * 32 + fm * 16 + gid;
        float d0 = 0.f, d1 = 0.f;
        if (M_FROM_TAB) { d0 = dist[row]; d1 = dist[row + 8]; }
#pragma unroll
        for (int fn = 0; fn < 4; fn++) {
            int col = wn * 32 + fn * 8 + tg * 2;
            float2 b0, b1;
            if (M_FROM_TAB) {
                b0 = tab_lerp2(g_tabm, d0, col);
                b1 = tab_lerp2(g_tabm, d1, col);
            } else {
                b0 = *(const float2*)(m_old + (size_t)row * 128 + col);
                b1 = *(const float2*)(m_old + (size_t)(row + 8) * 128 + col);
            }
            b0.x += msum[fm][fn][0];
            b0.y += msum[fm][fn][1];
            *(float2*)(m_new + (size_t)row * 128 + col) = b0;
            b1.x += msum[fm][fn][2];
            b1.y += msum[fm][fn][3];
            *(float2*)(m_new + (size_t)(row + 8) * 128 + col) = b1;
        }
    }
}

// ---------------- CSR triplet aggregation (last iteration, atomic-free) ----------------
__global__ void triplet_csr_kernel(const int* __restrict__ trip, const float* __restrict__ dist,
                                   const float* __restrict__ ang, const float* __restrict__ tab,
                                   const float* __restrict__ m_src, float* __restrict__ agg)
{
    int a = (blockIdx.x * blockDim.x + threadIdx.x) >> 5;
    int lane = threadIdx.x & 31;
    if (a >= NATOM) return;
    int b0 = g_csr_off[a], b1 = g_csr_off[a + 1];
    float4 acc = make_float4(0.f, 0.f, 0.f, 0.f);
#pragma unroll 2
    for (int idx = b0; idx < b1; idx++) {
        int gw = g_csr_edge[idx];
        int ji = trip[gw * 3 + 0];
        int kj = trip[gw * 3 + 1];
        float aw = ang[ji];
        float4 mv = ((const float4*)(m_src + (size_t)kj * HID))[lane];
        float4 rv = tab_lerp_t(tab, dist[kj], lane);
        acc.x += mv.x * rv.x * aw;
        acc.y += mv.y * rv.y * aw;
        acc.z += mv.z * rv.z * aw;
        acc.w += mv.w * rv.w * aw;
    }
    ((float4*)(agg + (size_t)a * HID))[lane] = acc;
}

// ---------------- host launcher ----------------
extern "C" void kernel_launch(void* const* d_in, const int* in_sizes, int n_in,
                              void* d_out, int out_size)
{
    const int*   Z        = (const int*)d_in[0];
    const int*   ei       = (const int*)d_in[1];
    const float* dist     = (const float*)d_in[2];
    const float* dirs     = (const float*)d_in[3];
    const int*   trip     = (const int*)d_in[4];
    const float* atom_emb = (const float*)d_in[5];
    const float* embed_w  = (const float*)d_in[6];
    const float* embed_b  = (const float*)d_in[7];
    const float* ib_rad_w1 = (const float*)d_in[8];
    const float* ib_rad_b1 = (const float*)d_in[9];
    const float* ib_rad_w2 = (const float*)d_in[10];
    const float* ib_rad_b2 = (const float*)d_in[11];
    const float* ib_sph_w  = (const float*)d_in[12];
    const float* ib_sph_b  = (const float*)d_in[13];
    const float* ib_upd_w1 = (const float*)d_in[14];
    const float* ib_upd_b1 = (const float*)d_in[15];
    const float* ib_upd_w2 = (const float*)d_in[16];
    const float* ib_upd_b2 = (const float*)d_in[17];
    const float* ib_out_w  = (const float*)d_in[18];
    const float* ib_out_b  = (const float*)d_in[19];
    const float* ob_rad_w1 = (const float*)d_in[20];
    const float* ob_rad_b1 = (const float*)d_in[21];
    const float* ob_rad_w2 = (const float*)d_in[22];
    const float* ob_rad_b2 = (const float*)d_in[23];
    const float* ob_dense_w = (const float*)d_in[24];
    const float* ob_dense_b = (const float*)d_in[25];
    const float* ob_out_w  = (const float*)d_in[26];
    const float* ob_out_b  = (const float*)d_in[27];
    float* out = (float*)d_out;

    float *p_agg, *p_m0, *p_m1, *p_tabs, *p_ang;
    __nv_bfloat16 *p_wbh, *p_wbl;
    int *p_cnt, *p_pos;
    cudaGetSymbolAddress((void**)&p_m0,   g_m);
    cudaGetSymbolAddress((void**)&p_m1,   g_m2);
    cudaGetSymbolAddress((void**)&p_agg,  g_agg);
    cudaGetSymbolAddress((void**)&p_tabs, g_tabs);
    cudaGetSymbolAddress((void**)&p_ang,  g_ang4);
    cudaGetSymbolAddress((void**)&p_wbh,  g_wbh);
    cudaGetSymbolAddress((void**)&p_wbl,  g_wbl);
    cudaGetSymbolAddress((void**)&p_cnt,  g_csr_cnt);
    cudaGetSymbolAddress((void**)&p_pos,  g_csr_pos);
    float* mBuf[2] = { p_m0, p_m1 };

    cudaFuncSetAttribute(rad_mlp_batch_kernel, cudaFuncAttributeMaxDynamicSharedMemorySize, RAD_SMEM);
    cudaFuncSetAttribute(fused_trip_mma_kernel<true >, cudaFuncAttributeMaxDynamicSharedMemorySize, FUSED_SMEM);
    cudaFuncSetAttribute(fused_trip_mma_kernel<false>, cudaFuncAttributeMaxDynamicSharedMemorySize, FUSED_SMEM);
    cudaFuncSetAttribute(hupdate_kernel, cudaFuncAttributeMaxDynamicSharedMemorySize, HUPD_SMEM);
    cudaFuncSetAttribute(outblock_kernel<false>, cudaFuncAttributeMaxDynamicSharedMemorySize, OUT_SMEM);
    cudaFuncSetAttribute(outblock_kernel<true >, cudaFuncAttributeMaxDynamicSharedMemorySize, OUT_SMEM);

    const int GT = NTAB / 64;             // 128
    const int GA = (NATOM + 63) / 64;     // 157
    const int GM = NEDGE / 128;           // 2500
    const int GC = (NATOM * 32 + 255) / 256;
    const size_t AGG_BYTES = (size_t)NATOM * HID * sizeof(float);
    const size_t TABSZ = (size_t)NTAB * HID;

    cudaStream_t sB;
    cudaStreamCreateWithFlags(&sB, cudaStreamNonBlocking);
    cudaEvent_t eTab, eTm, eCSR, eTabs, eF[4];
    cudaEventCreateWithFlags(&eTab, cudaEventDisableTiming);
    cudaEventCreateWithFlags(&eTm, cudaEventDisableTiming);
    cudaEventCreateWithFlags(&eCSR, cudaEventDisableTiming);
    cudaEventCreateWithFlags(&eTabs, cudaEventDisableTiming);
    for (int i = 0; i < 4; i++) cudaEventCreateWithFlags(&eF[i], cudaEventDisableTiming);

    // ---- A prologue: rbf table, CSR build, m table ----
    tab_prep_kernel<<<NTAB / 256, 256>>>();
    cudaEventRecord(eTab, 0);
    cudaMemsetAsync(p_cnt, 0, NATOM * sizeof(int));
    cudaMemsetAsync(p_pos, 0, NATOM * sizeof(int));
    csr_count_kernel<<<(NEDGE + 255) / 256, 256>>>(ei);
    csr_scan_kernel<<<1, 1024>>>();
    csr_fill_kernel<<<(NEDGE + 255) / 256, 256>>>(ei);
    cudaEventRecord(eCSR, 0);
    tabm_kernel<<<NTAB / 8, 256>>>(embed_w, embed_b);
    cudaEventRecord(eTm, 0);

    // ---- B prologue: angles, weights, h, all 9 radial tables ----
    {
        dim3 ga((NEDGE + 255) / 256, 4);
        angle_batch_kernel<<<ga, 256, 0, sB>>>(ib_sph_w, ib_sph_b, dirs);
    }
    cudaStreamWaitEvent(sB, eTab, 0);
    wsplit_kernel<<<(9 * HID * HID + 255) / 256, 256, 0, sB>>>(ib_out_w);
    h_init_kernel<<<(NATOM * 32 + 255) / 256, 256, 0, sB>>>(Z, atom_emb);
    {
        dim3 gr(GT, 9);
        rad_mlp_batch_kernel<<<gr, 256, RAD_SMEM, sB>>>(ob_rad_w1, ob_rad_b1, ob_rad_w2, ob_rad_b2,
                                                        ib_rad_w1, ib_rad_b1, ib_rad_w2, ib_rad_b2);
    }
    cudaEventRecord(eTabs, sB);

    // ---- B: zero agg buffers, free-running fused chain ----
    cudaMemsetAsync(p_agg, 0, 3 * AGG_BYTES, sB);
    cudaStreamWaitEvent(sB, eTm, 0);   // tabm ready for fused<true>
    fused_trip_mma_kernel<true><<<GM, 512, FUSED_SMEM, sB>>>(trip, ei, dist,
        p_ang, p_tabs + (size_t)5 * TABSZ,
        mBuf[0] /*unused*/, mBuf[1], p_agg,
        p_wbh, p_wbl, ib_out_b);
    cudaEventRecord(eF[0], sB);
    for (int i = 1; i < 3; i++) {
        fused_trip_mma_kernel<false><<<GM, 512, FUSED_SMEM, sB>>>(trip, ei, dist,
            p_ang + (size_t)i * NEDGE, p_tabs + (size_t)(5 + i) * TABSZ,
            mBuf[i & 1], mBuf[(i + 1) & 1], p_agg + (size_t)i * NATOM * HID,
            p_wbh + (size_t)i * 3 * 16384, p_wbl + (size_t)i * 3 * 16384,
            ib_out_b + i * 3 * 128);
        cudaEventRecord(eF[i], sB);
    }
    cudaStreamWaitEvent(sB, eCSR, 0);
    triplet_csr_kernel<<<GC, 256, 0, sB>>>(trip, dist, p_ang + (size_t)3 * NEDGE,
                                           p_tabs + (size_t)8 * TABSZ,
                                           mBuf[1], p_agg + (size_t)3 * NATOM * HID);
    cudaEventRecord(eF[3], sB);

    // ---- A: output block 0 (h + tables done at eTabs; CSR ordered on A) ----
    cudaStreamWaitEvent(0, eTabs, 0);
    outblock_kernel<false><<<GA, 256, OUT_SMEM>>>(ei, dist, p_tabs,
        ob_dense_w, ob_dense_b, ob_out_w, ob_out_b, out, NATOM);

    for (int i = 0; i < 4; i++) {
        cudaStreamWaitEvent(0, eF[i], 0);
        hupdate_kernel<<<GA, 256, HUPD_SMEM>>>(p_agg + (size_t)i * NATOM * HID,
                                               ib_upd_w1 + (size_t)i * 32768, ib_upd_b1 + i * 128,
                                               ib_upd_w2 + (size_t)i * 16384, ib_upd_b2 + i * 128, NATOM);
        int ob = i + 1;
        outblock_kernel<true><<<GA, 256, OUT_SMEM>>>(ei, dist, p_tabs + (size_t)ob * TABSZ,
            ob_dense_w + (size_t)ob * 3 * 16384, ob_dense_b + ob * 3 * 128,
            ob_out_w + ob * 128, ob_out_b + ob, out, NATOM);
    }
}

// round 16
// speedup vs baseline: 1.0415x; 1.0415x over previous
#include <cuda_runtime.h>
#include <cuda_bf16.h>
#include <math_constants.h>

#define NEDGE 320000
#define NATOM 10000
#define HID   128
#define CUT   5.0f
#define NTAB  8192

typedef unsigned long long u64;
typedef unsigned int u32;

// ---------------- scratch (static device memory; no allocations) ----------------
__device__ __align__(16) float g_m   [(size_t)NEDGE * HID];   // m buffer 0
__device__ __align__(16) float g_m2  [(size_t)NEDGE * HID];   // m buffer 1
__device__ __align__(16) float g_ang4[(size_t)4 * NEDGE];
__device__ __align__(16) float g_h   [(size_t)NATOM * HID];
__device__ __align__(16) float g_agg [4][(size_t)NATOM * HID];
__device__ __align__(16) float g_x   [(size_t)NATOM * HID];
__device__ __align__(16) float g_tabrbf[(size_t)NTAB * 16];
__device__ __align__(16) float g_tabs[(size_t)9 * NTAB * HID];  // 0..4 ob, 5..8 ib
__device__ __align__(16) float g_tabm[(size_t)NTAB * HID];
__device__ __align__(16) __nv_bfloat16 g_wbh[(size_t)9 * HID * HID];
__device__ __align__(16) __nv_bfloat16 g_wbl[(size_t)9 * HID * HID];
__device__ int g_csr_cnt [NATOM];
__device__ int g_csr_pos [NATOM];
__device__ int g_csr_off [NATOM + 1];
__device__ int g_csr_edge[NEDGE];

__device__ __forceinline__ float silu_f(float x) { return x / (1.0f + __expf(-x)); }

__device__ __forceinline__ void red_add_v4(float* p, float4 v)
{
    asm volatile("red.global.add.v4.f32 [%0], {%1,%2,%3,%4};"
                 :: "l"(p), "f"(v.x), "f"(v.y), "f"(v.z), "f"(v.w) : "memory");
}

// ---------------- packed f32x2 helpers ----------------
__device__ __forceinline__ u64 pack2(float a) {
    u64 r; asm("mov.b64 %0, {%1, %1};" : "=l"(r) : "f"(a)); return r;
}
__device__ __forceinline__ void fma2(u64& d, u64 a, u64 b) {
    asm("fma.rn.f32x2 %0, %1, %2, %3;" : "=l"(d) : "l"(a), "l"(b), "l"(d));
}
__device__ __forceinline__ float2 unpack2(u64 v) {
    float2 f; asm("mov.b64 {%0, %1}, %2;" : "=f"(f.x), "=f"(f.y) : "l"(v)); return f;
}

// ---------------- bessel rbf ----------------
__device__ __forceinline__ void rbf_eval(float d, float* out16)
{
    float x = d * (1.0f / CUT);
    float x2 = x * x;
    float x6 = x2 * x2 * x2;
    float x7 = x6 * x;
    float x8 = x7 * x;
    float env = 1.0f - 28.0f * x6 + 48.0f * x7 - 21.0f * x8;
    if (!(d < CUT)) env = 0.0f;
    float s = sqrtf(2.0f / CUT) / d * env;
    float base = (float)CUDART_PI_F / CUT * d;
#pragma unroll
    for (int k = 0; k < 16; k++)
        out16[k] = s * sinf(base * (float)(k + 1));
}

__global__ void tab_prep_kernel()
{
    int i = blockIdx.x * blockDim.x + threadIdx.x;
    if (i >= NTAB) return;
    float d = fmaxf((float)i * (CUT / (float)(NTAB - 1)), 1e-4f);
    float r16[16];
    rbf_eval(d, r16);
#pragma unroll
    for (int k = 0; k < 16; k++) g_tabrbf[(size_t)i * 16 + k] = r16[k];
}

__device__ __forceinline__ float4 tab_lerp_t(const float* tab, float d, int lane)
{
    float t = d * ((float)(NTAB - 1) / CUT);
    int i0 = min((int)t, NTAB - 2);
    float f = t - (float)i0;
    float4 lo = ((const float4*)(tab + (size_t)i0 * HID))[lane];
    float4 hi = ((const float4*)(tab + (size_t)(i0 + 1) * HID))[lane];
    float4 o;
    o.x = lo.x + (hi.x - lo.x) * f;
    o.y = lo.y + (hi.y - lo.y) * f;
    o.z = lo.z + (hi.z - lo.z) * f;
    o.w = lo.w + (hi.w - lo.w) * f;
    return o;
}

__device__ __forceinline__ float2 tab_lerp2(const float* tab, float d, int col)
{
    float t = d * ((float)(NTAB - 1) / CUT);
    int i0 = min((int)t, NTAB - 2);
    float f = t - (float)i0;
    float2 lo = *(const float2*)(tab + (size_t)i0 * HID + col);
    float2 hi = *(const float2*)(tab + (size_t)(i0 + 1) * HID + col);
    return make_float2(lo.x + (hi.x - lo.x) * f, lo.y + (hi.y - lo.y) * f);
}

// ---------------- CSR build ----------------
__global__ void csr_count_kernel(const int* __restrict__ ei)
{
    int e = blockIdx.x * blockDim.x + threadIdx.x;
    if (e >= NEDGE) return;
    atomicAdd(&g_csr_cnt[ei[NEDGE + e]], 1);
}

__global__ void csr_scan_kernel()
{
    __shared__ int part[1024];
    const int tid = threadIdx.x;
    const int base = tid * 10;
    int s = 0;
#pragma unroll
    for (int k = 0; k < 10; k++) {
        int idx = base + k;
        if (idx < NATOM) s += g_csr_cnt[idx];
    }
    part[tid] = s;
    __syncthreads();
    for (int off = 1; off < 1024; off <<= 1) {
        int v = 0;
        if (tid >= off) v = part[tid - off];
        __syncthreads();
        part[tid] += v;
        __syncthreads();
    }
    int run = part[tid] - s;
#pragma unroll
    for (int k = 0; k < 10; k++) {
        int idx = base + k;
        if (idx < NATOM) {
            g_csr_off[idx] = run;
            run += g_csr_cnt[idx];
        }
    }
    if (tid == 1023) g_csr_off[NATOM] = run;
}

__global__ void csr_fill_kernel(const int* __restrict__ ei)
{
    int e = blockIdx.x * blockDim.x + threadIdx.x;
    if (e >= NEDGE) return;
    int dd = ei[NEDGE + e];
    int p = atomicAdd(&g_csr_pos[dd], 1);
    g_csr_edge[g_csr_off[dd] + p] = e;
}

// ---------------- m table ----------------
__global__ void tabm_kernel(const float* __restrict__ embed_w, const float* __restrict__ embed_b)
{
    __shared__ float Ws[16 * 128];
    __shared__ float bs[128];
    __shared__ float rs[8 * 16];
    int tid = threadIdx.x;
    for (int i = tid; i < 2048; i += 256)
        Ws[i] = embed_w[(i >> 7) * 384 + 256 + (i & 127)];
    if (tid < 128) bs[tid] = embed_b[256 + tid];
    int e0 = blockIdx.x * 8;
    if (tid < 128) rs[tid] = g_tabrbf[(size_t)e0 * 16 + tid];
    __syncthreads();
    int w = tid >> 5, lane = tid & 31;
    int e = e0 + w;
    float4 acc = *(const float4*)&bs[lane * 4];
#pragma unroll
    for (int k = 0; k < 16; k++) {
        float a = rs[w * 16 + k];
        float4 wv = *(const float4*)&Ws[k * 128 + lane * 4];
        acc.x += a * wv.x; acc.y += a * wv.y; acc.z += a * wv.z; acc.w += a * wv.w;
    }
    ((float4*)(g_tabm + (size_t)e * HID))[lane] = acc;
}

// ---------------- pre-split ib_out_w ----------------
__global__ void wsplit_kernel(const float* __restrict__ W)
{
    int i = blockIdx.x * blockDim.x + threadIdx.x;
    if (i >= 9 * HID * HID) return;
    int mat = i >> 14;
    int r = i & 16383;
    int k = r >> 7, n = r & 127;
    float w = W[i];
    __nv_bfloat16 h = __float2bfloat16(w);
    float rr = w - __bfloat162float(h);
    size_t o = (size_t)mat * 16384 + n * 128 + k;
    g_wbh[o] = h;
    g_wbl[o] = __float2bfloat16(rr);
}

__global__ void h_init_kernel(const int* __restrict__ Z, const float* __restrict__ emb)
{
    int idx = blockIdx.x * blockDim.x + threadIdx.x;
    int a = idx >> 5, lane = idx & 31;
    if (a >= NATOM) return;
    int z = Z[a] - 1;
    ((float4*)(g_h + (size_t)a * HID))[lane] =
        ((const float4*)(emb + (size_t)z * HID))[lane];
}

// ---------------- batched angle ----------------
__global__ void angle_batch_kernel(const float* __restrict__ sphW, const float* __restrict__ sphB,
                                   const float* __restrict__ dirs)
{
    __shared__ float wbar[8];
    __shared__ float bbar;
    const int inst = blockIdx.y;
    const float* W = sphW + inst * 56;
    const float* B = sphB + inst * 8;
    if (threadIdx.x < 7) {
        float s = 0.0f;
#pragma unroll
        for (int j = 0; j < 8; j++) s += W[threadIdx.x * 8 + j];
        wbar[threadIdx.x] = s * 0.125f;
    }
    if (threadIdx.x == 7) {
        float s = 0.0f;
#pragma unroll
        for (int j = 0; j < 8; j++) s += B[j];
        bbar = s * 0.125f;
    }
    __syncthreads();
    int e = blockIdx.x * blockDim.x + threadIdx.x;
    if (e >= NEDGE) return;
    float dx = dirs[e * 3 + 0], dy = dirs[e * 3 + 1], dz = dirs[e * 3 + 2];
    float acc = bbar + wbar[0] + wbar[1] * dy + wbar[2] * dz + wbar[3] * dx
              + wbar[4] * dx * dy + wbar[5] * dy * dz + wbar[6] * (3.0f * dz * dz - 1.0f);
    g_ang4[(size_t)inst * NEDGE + e] = 1.0f / (1.0f + __expf(-acc));
}

// ---------------- SIMT GEMM core ----------------
__device__ __forceinline__ void gemm_core8(const float* __restrict__ Ws,
                                           const float* __restrict__ Xs,
                                           u64 acc[4][4], int tx, int ty)
{
#pragma unroll 2
    for (int k0 = 0; k0 < 128; k0 += 4) {
        float4 av[4];
#pragma unroll
        for (int r = 0; r < 4; r++)
            av[r] = *(const float4*)(Xs + (ty * 4 + r) * 128 + k0);
#pragma unroll
        for (int kk = 0; kk < 4; kk++) {
            ulonglong2 b01 = *(const ulonglong2*)(Ws + (k0 + kk) * 128 + tx * 8);
            ulonglong2 b23 = *(const ulonglong2*)(Ws + (k0 + kk) * 128 + tx * 8 + 4);
#pragma unroll
            for (int r = 0; r < 4; r++) {
                float aval = ((const float*)&av[r])[kk];
                u64 ap = pack2(aval);
                fma2(acc[r][0], ap, b01.x);
                fma2(acc[r][1], ap, b01.y);
                fma2(acc[r][2], ap, b23.x);
                fma2(acc[r][3], ap, b23.y);
            }
        }
    }
}

// ---------------- batched radial MLP ----------------
#define RAD_SMEM ((16384 + 8192 + 2048 + 128 + 1024) * 4)
__global__ void __launch_bounds__(256, 2) rad_mlp_batch_kernel(
    const float* __restrict__ ob_w1, const float* __restrict__ ob_b1,
    const float* __restrict__ ob_w2, const float* __restrict__ ob_b2,
    const float* __restrict__ ib_w1, const float* __restrict__ ib_b1,
    const float* __restrict__ ib_w2, const float* __restrict__ ib_b2)
{
    extern __shared__ float sm[];
    float* W2s = sm;
    float* Hs  = sm + 16384;
    float* W1s = sm + 16384 + 8192;
    float* b1s = W1s + 2048;
    float* Rs  = b1s + 128;
    const int tid = threadIdx.x;
    const int row0 = blockIdx.x * 64;
    const int inst = blockIdx.y;
    const float *rW1, *rb1, *rW2, *rb2;
    if (inst < 5) {
        rW1 = ob_w1 + (size_t)inst * 2048;  rb1 = ob_b1 + inst * 128;
        rW2 = ob_w2 + (size_t)inst * 16384; rb2 = ob_b2 + inst * 128;
    } else {
        int i = inst - 5;
        rW1 = ib_w1 + (size_t)i * 2048;  rb1 = ib_b1 + i * 128;
        rW2 = ib_w2 + (size_t)i * 16384; rb2 = ib_b2 + i * 128;
    }
    float* Y = g_tabs + (size_t)inst * NTAB * HID;

    for (int i = tid; i < 4096; i += 256) ((float4*)W2s)[i] = ((const float4*)rW2)[i];
    for (int i = tid; i < 512;  i += 256) ((float4*)W1s)[i] = ((const float4*)rW1)[i];
    if (tid < 32) ((float4*)b1s)[tid] = ((const float4*)rb1)[tid];
    {
        int r = tid >> 2;
        ((float4*)Rs)[tid] = ((const float4*)(g_tabrbf + (size_t)(row0 + r) * 16))[tid & 3];
    }
    __syncthreads();
    {
        const int tx5 = tid & 31, ty5 = tid >> 5;
        float4 b1v = *(const float4*)&b1s[tx5 * 4];
#pragma unroll
        for (int i = 0; i < 8; i++) {
            int r = ty5 * 8 + i;
            float4 a4 = b1v;
#pragma unroll
            for (int k = 0; k < 16; k++) {
                float a = Rs[r * 16 + k];
                float4 w = *(const float4*)&W1s[k * 128 + tx5 * 4];
                a4.x += a * w.x; a4.y += a * w.y; a4.z += a * w.z; a4.w += a * w.w;
            }
            a4.x = silu_f(a4.x); a4.y = silu_f(a4.y); a4.z = silu_f(a4.z); a4.w = silu_f(a4.w);
            *(float4*)&Hs[r * 128 + tx5 * 4] = a4;
        }
    }
    __syncthreads();
    const int tx = tid & 15, ty = tid >> 4;
    u64 acc[4][4];
#pragma unroll
    for (int r = 0; r < 4; r++)
#pragma unroll
        for (int c = 0; c < 4; c++) acc[r][c] = 0ull;
    gemm_core8(W2s, Hs, acc, tx, ty);
    float4 blo = *(const float4*)(rb2 + tx * 8);
    float4 bhi = *(const float4*)(rb2 + tx * 8 + 4);
#pragma unroll
    for (int r = 0; r < 4; r++) {
        int row = ty * 4 + r;
        float2 p0 = unpack2(acc[r][0]);
        float2 p1 = unpack2(acc[r][1]);
        float2 p2 = unpack2(acc[r][2]);
        float2 p3 = unpack2(acc[r][3]);
        float* yp = Y + (size_t)(row0 + row) * 128 + tx * 8;
        *(float4*)yp       = make_float4(p0.x + blo.x, p0.y + blo.y, p1.x + blo.z, p1.y + blo.w);
        *(float4*)(yp + 4) = make_float4(p2.x + bhi.x, p2.y + bhi.y, p3.x + bhi.z, p3.y + bhi.w);
    }
}

// ---------------- fused h update ----------------
#define HUPD_SMEM ((16384 + 8192) * 4)
__global__ void __launch_bounds__(256, 2) hupdate_kernel(const float* __restrict__ agg,
                                                         const float* __restrict__ w1,
                                                         const float* __restrict__ b1,
                                                         const float* __restrict__ w2,
                                                         const float* __restrict__ b2,
                                                         int nrows)
{
    extern __shared__ float sm[];
    float* Ws = sm;
    float* Xs = sm + 16384;
    const int tid = threadIdx.x;
    const int row0 = blockIdx.x * 64;
    const int rows = min(64, nrows - row0);
    const int tx = tid & 15, ty = tid >> 4;

    for (int i = tid; i < 2048; i += 256) {
        int r = i >> 5, c = i & 31;
        float4 v = make_float4(0.f, 0.f, 0.f, 0.f);
        if (r < rows) v = ((const float4*)(g_h + (size_t)(row0 + r) * 128))[c];
        ((float4*)Xs)[i] = v;
    }
    for (int i = tid; i < 4096; i += 256) ((float4*)Ws)[i] = ((const float4*)w1)[i];
    __syncthreads();
    u64 acc[4][4];
#pragma unroll
    for (int r = 0; r < 4; r++)
#pragma unroll
        for (int c = 0; c < 4; c++) acc[r][c] = 0ull;
    gemm_core8(Ws, Xs, acc, tx, ty);
    __syncthreads();

    for (int i = tid; i < 2048; i += 256) {
        int r = i >> 5, c = i & 31;
        float4 v = make_float4(0.f, 0.f, 0.f, 0.f);
        if (r < rows) v = ((const float4*)(agg + (size_t)(row0 + r) * 128))[c];
        ((float4*)Xs)[i] = v;
    }
    for (int i = tid; i < 4096; i += 256) ((float4*)Ws)[i] = ((const float4*)(w1 + 16384))[i];
    __syncthreads();
    gemm_core8(Ws, Xs, acc, tx, ty);
    __syncthreads();

    {
        float4 blo = *(const float4*)(b1 + tx * 8);
        float4 bhi = *(const float4*)(b1 + tx * 8 + 4);
#pragma unroll
        for (int r = 0; r < 4; r++) {
            int row = ty * 4 + r;
            float2 p0 = unpack2(acc[r][0]);
            float2 p1 = unpack2(acc[r][1]);
            float2 p2 = unpack2(acc[r][2]);
            float2 p3 = unpack2(acc[r][3]);
            *(float4*)&Xs[row * 128 + tx * 8] =
                make_float4(silu_f(p0.x + blo.x), silu_f(p0.y + blo.y),
                            silu_f(p1.x + blo.z), silu_f(p1.y + blo.w));
            *(float4*)&Xs[row * 128 + tx * 8 + 4] =
                make_float4(silu_f(p2.x + bhi.x), silu_f(p2.y + bhi.y),
                            silu_f(p3.x + bhi.z), silu_f(p3.y + bhi.w));
        }
    }
    for (int i = tid; i < 4096; i += 256) ((float4*)Ws)[i] = ((const float4*)w2)[i];
    __syncthreads();

#pragma unroll
    for (int r = 0; r < 4; r++)
#pragma unroll
        for (int c = 0; c < 4; c++) acc[r][c] = 0ull;
    gemm_core8(Ws, Xs, acc, tx, ty);
    {
        float4 blo = *(const float4*)(b2 + tx * 8);
        float4 bhi = *(const float4*)(b2 + tx * 8 + 4);
#pragma unroll
        for (int r = 0; r < 4; r++) {
            int row = ty * 4 + r;
            if (row >= rows) break;
            float2 p0 = unpack2(acc[r][0]);
            float2 p1 = unpack2(acc[r][1]);
            float2 p2 = unpack2(acc[r][2]);
            float2 p3 = unpack2(acc[r][3]);
            float* hp = g_h + (size_t)(row0 + row) * 128 + tx * 8;
            float4 u0 = *(float4*)hp;
            float4 u1 = *(float4*)(hp + 4);
            u0.x += p0.x + blo.x; u0.y += p0.y + blo.y; u0.z += p1.x + blo.z; u0.w += p1.y + blo.w;
            u1.x += p2.x + bhi.x; u1.y += p2.y + bhi.y; u1.z += p3.x + bhi.z; u1.w += p3.y + bhi.w;
            *(float4*)hp = u0;
            *(float4*)(hp + 4) = u1;
        }
    }
}

// ---------------- fused output block (reads g_x) ----------------
#define OUT_SMEM ((16384 + 8192 + 128) * 4)
template<bool ACCUM>
__global__ void __launch_bounds__(256, 2) outblock_kernel(const float* __restrict__ dw,
                                                          const float* __restrict__ db,
                                                          const float* __restrict__ ow,
                                                          const float* __restrict__ obias,
                                                          float* __restrict__ out, int nrows)
{
    extern __shared__ float sm[];
    float* Ws   = sm;
    float* Xs   = sm + 16384;
    float* wout = sm + 16384 + 8192;
    const int tid = threadIdx.x;
    const int row0 = blockIdx.x * 64;
    const int rows = min(64, nrows - row0);
    const int tx = tid & 15, ty = tid >> 4;

    if (tid < 32) ((float4*)wout)[tid] = ((const float4*)ow)[tid];
    for (int i = tid; i < 2048; i += 256) {
        int r = i >> 5, c = i & 31;
        float4 v = make_float4(0.f, 0.f, 0.f, 0.f);
        if (r < rows) v = ((const float4*)(g_x + (size_t)(row0 + r) * 128))[c];
        ((float4*)Xs)[i] = v;
    }

    for (int j = 0; j < 3; j++) {
        __syncthreads();
        for (int i = tid; i < 4096; i += 256)
            ((float4*)Ws)[i] = ((const float4*)(dw + (size_t)j * 16384))[i];
        __syncthreads();
        u64 acc[4][4];
#pragma unroll
        for (int r = 0; r < 4; r++)
#pragma unroll
            for (int c = 0; c < 4; c++) acc[r][c] = 0ull;
        gemm_core8(Ws, Xs, acc, tx, ty);
        __syncthreads();
        float4 blo = *(const float4*)(db + j * 128 + tx * 8);
        float4 bhi = *(const float4*)(db + j * 128 + tx * 8 + 4);
#pragma unroll
        for (int r = 0; r < 4; r++) {
            int row = ty * 4 + r;
            float2 p0 = unpack2(acc[r][0]);
            float2 p1 = unpack2(acc[r][1]);
            float2 p2 = unpack2(acc[r][2]);
            float2 p3 = unpack2(acc[r][3]);
            *(float4*)&Xs[row * 128 + tx * 8] =
                make_float4(silu_f(p0.x + blo.x), silu_f(p0.y + blo.y),
                            silu_f(p1.x + blo.z), silu_f(p1.y + blo.w));
            *(float4*)&Xs[row * 128 + tx * 8 + 4] =
                make_float4(silu_f(p2.x + bhi.x), silu_f(p2.y + bhi.y),
                            silu_f(p3.x + bhi.z), silu_f(p3.y + bhi.w));
        }
    }
    __syncthreads();

    const int wid = tid >> 5, lane = tid & 31;
    float bias0 = obias[0];
    float4 wv = *(const float4*)&wout[lane * 4];
#pragma unroll
    for (int r8 = 0; r8 < 8; r8++) {
        int row = wid * 8 + r8;
        float4 xv = *(const float4*)&Xs[row * 128 + lane * 4];
        float s = xv.x * wv.x + xv.y * wv.y + xv.z * wv.z + xv.w * wv.w;
#pragma unroll
        for (int off = 16; off > 0; off >>= 1) s += __shfl_xor_sync(0xFFFFFFFFu, s, off);
        if (lane == 0 && row < rows) {
            float v = s + bias0;
            if (ACCUM) out[row0 + row] += v; else out[row0 + row] = v;
        }
    }
}

// ---------------- FUSED triplet + bf16-split tensor GEMM x3 + m update (512 threads) ----------------
#define FUSED_SMEM (4 * 128 * 136 * 2)
__device__ __forceinline__ void mma_bf16(float* c, const u32* a, const u32* b)
{
    asm volatile("mma.sync.aligned.m16n8k16.row.col.f32.bf16.bf16.f32 "
                 "{%0,%1,%2,%3}, {%4,%5,%6,%7}, {%8,%9}, {%0,%1,%2,%3};"
                 : "+f"(c[0]), "+f"(c[1]), "+f"(c[2]), "+f"(c[3])
                 : "r"(a[0]), "r"(a[1]), "r"(a[2]), "r"(a[3]), "r"(b[0]), "r"(b[1]));
}

template<bool M_FROM_TAB>
__global__ void __launch_bounds__(512, 1) fused_trip_mma_kernel(
    const int* __restrict__ trip, const int* __restrict__ ei, const float* __restrict__ dist,
    const float* __restrict__ ang, const float* __restrict__ tab,
    const float* __restrict__ m_old, float* __restrict__ m_new, float* __restrict__ agg,
    const __nv_bfloat16* __restrict__ Wh3, const __nv_bfloat16* __restrict__ Wl3,
    const float* __restrict__ bias3)
{
    extern __shared__ __nv_bfloat16 smb[];
    __nv_bfloat16* sAh = smb;                 // [128][136]
    __nv_bfloat16* sAl = smb + 128 * 136;
    __nv_bfloat16* sBh = smb + 2 * 128 * 136;
    __nv_bfloat16* sBl = smb + 3 * 128 * 136;
    const int tid = threadIdx.x;
    const int row0 = blockIdx.x * 128;
    const int lane = tid & 31, wid = tid >> 5;   // 16 warps

    // ---- phase 1: triplet gather (8 rows per warp) ----
#pragma unroll 4
    for (int rr = 0; rr < 8; rr++) {
        int r = wid * 8 + rr;
        int gw = row0 + r;
        int ji = trip[gw * 3 + 0];
        int kj = trip[gw * 3 + 1];
        float aw = ang[ji];
        float dkj = dist[kj];
        float4 mv;
        if (M_FROM_TAB) mv = tab_lerp_t(g_tabm, dkj, lane);
        else            mv = ((const float4*)(m_old + (size_t)kj * HID))[lane];
        float4 rv = tab_lerp_t(tab, dkj, lane);
        float4 o = make_float4(mv.x * rv.x * aw, mv.y * rv.y * aw,
                               mv.z * rv.z * aw, mv.w * rv.w * aw);
        int dd = ei[NEDGE + gw];
        red_add_v4(agg + (size_t)dd * HID + lane * 4, o);

        __nv_bfloat162 h01, h23, l01, l23;
        h01.x = __float2bfloat16(o.x); h01.y = __float2bfloat16(o.y);
        h23.x = __float2bfloat16(o.z); h23.y = __float2bfloat16(o.w);
        l01.x = __float2bfloat16(o.x - __bfloat162float(h01.x));
        l01.y = __float2bfloat16(o.y - __bfloat162float(h01.y));
        l23.x = __float2bfloat16(o.z - __bfloat162float(h23.x));
        l23.y = __float2bfloat16(o.w - __bfloat162float(h23.y));
        *(__nv_bfloat162*)&sAh[r * 136 + lane * 4]     = h01;
        *(__nv_bfloat162*)&sAh[r * 136 + lane * 4 + 2] = h23;
        *(__nv_bfloat162*)&sAl[r * 136 + lane * 4]     = l01;
        *(__nv_bfloat162*)&sAl[r * 136 + lane * 4 + 2] = l23;
    }

    // ---- phase 2: 3 tensor GEMMs, warp grid 4x4 ----
    const int wm = wid >> 2, wn = wid & 3;
    const int gid = lane >> 2, tg = lane & 3;

    float msum[2][4][4];
#pragma unroll
    for (int a = 0; a < 2; a++)
#pragma unroll
        for (int b = 0; b < 4; b++)
#pragma unroll
            for (int c = 0; c < 4; c++) msum[a][b][c] = 0.0f;

    for (int j = 0; j < 3; j++) {
        __syncthreads();
        {
            const uint4* Wh4 = (const uint4*)(Wh3 + (size_t)j * 16384);
            const uint4* Wl4 = (const uint4*)(Wl3 + (size_t)j * 16384);
            for (int i = tid; i < 2048; i += 512) {
                int r = i >> 4, c = i & 15;
                *(uint4*)&sBh[r * 136 + c * 8] = Wh4[r * 16 + c];
                *(uint4*)&sBl[r * 136 + c * 8] = Wl4[r * 16 + c];
            }
        }
        __syncthreads();

        float acc[2][4][4];
#pragma unroll
        for (int a = 0; a < 2; a++)
#pragma unroll
            for (int b = 0; b < 4; b++)
#pragma unroll
                for (int c = 0; c < 4; c++) acc[a][b][c] = 0.0f;

#pragma unroll
        for (int ks = 0; ks < 8; ks++) {
            const int kb = ks * 16;
            u32 ah[2][4], al[2][4];
#pragma unroll
            for (int fm = 0; fm < 2; fm++) {
                int r = wm * 32 + fm * 16 + gid;
                ah[fm][0] = *(const u32*)&sAh[(r)     * 136 + kb + tg * 2];
                ah[fm][1] = *(const u32*)&sAh[(r + 8) * 136 + kb + tg * 2];
                ah[fm][2] = *(const u32*)&sAh[(r)     * 136 + kb + 8 + tg * 2];
                ah[fm][3] = *(const u32*)&sAh[(r + 8) * 136 + kb + 8 + tg * 2];
                al[fm][0] = *(const u32*)&sAl[(r)     * 136 + kb + tg * 2];
                al[fm][1] = *(const u32*)&sAl[(r + 8) * 136 + kb + tg * 2];
                al[fm][2] = *(const u32*)&sAl[(r)     * 136 + kb + 8 + tg * 2];
                al[fm][3] = *(const u32*)&sAl[(r + 8) * 136 + kb + 8 + tg * 2];
            }
            u32 bh[4][2], bl[4][2];
#pragma unroll
            for (int fn = 0; fn < 4; fn++) {
                int n = wn * 32 + fn * 8 + gid;
                bh[fn][0] = *(const u32*)&sBh[n * 136 + kb + tg * 2];
                bh[fn][1] = *(const u32*)&sBh[n * 136 + kb + 8 + tg * 2];
                bl[fn][0] = *(const u32*)&sBl[n * 136 + kb + tg * 2];
                bl[fn][1] = *(const u32*)&sBl[n * 136 + kb + 8 + tg * 2];
            }
#pragma unroll
            for (int fm = 0; fm < 2; fm++)
#pragma unroll
                for (int fn = 0; fn < 4; fn++) {
                    mma_bf16(acc[fm][fn], ah[fm], bh[fn]);
                    mma_bf16(acc[fm][fn], ah[fm], bl[fn]);
                    mma_bf16(acc[fm][fn], al[fm], bh[fn]);
                }
        }

        const float* bias = bias3 + j * 128;
#pragma unroll
        for (int fm = 0; fm < 2; fm++)
#pragma unroll
            for (int fn = 0; fn < 4; fn++) {
                int col = wn * 32 + fn * 8 + tg * 2;
                float2 b2 = *(const float2*)(bias + col);
                msum[fm][fn][0] += silu_f(acc[fm][fn][0] + b2.x);
                msum[fm][fn][1] += silu_f(acc[fm][fn][1] + b2.y);
                msum[fm][fn][2] += silu_f(acc[fm][fn][2] + b2.x);
                msum[fm][fn][3] += silu_f(acc[fm][fn][3] + b2.y);
            }
    }

    // ---- phase 3: m_new = m_old(base) + msum ----
#pragma unroll
    for (int fm = 0; fm < 2; fm++) {
        int row = row0 + wm * 32 + fm * 16 + gid;
        float d0 = 0.f, d1 = 0.f;
        if (M_FROM_TAB) { d0 = dist[row]; d1 = dist[row + 8]; }
#pragma unroll
        for (int fn = 0; fn < 4; fn++) {
            int col = wn * 32 + fn * 8 + tg * 2;
            float2 b0, b1;
            if (M_FROM_TAB) {
                b0 = tab_lerp2(g_tabm, d0, col);
                b1 = tab_lerp2(g_tabm, d1, col);
            } else {
                b0 = *(const float2*)(m_old + (size_t)row * 128 + col);
                b1 = *(const float2*)(m_old + (size_t)(row + 8) * 128 + col);
            }
            b0.x += msum[fm][fn][0];
            b0.y += msum[fm][fn][1];
            *(float2*)(m_new + (size_t)row * 128 + col) = b0;
            b1.x += msum[fm][fn][2];
            b1.y += msum[fm][fn][3];
            *(float2*)(m_new + (size_t)(row + 8) * 128 + col) = b1;
        }
    }
}

// ---------------- CSR triplet aggregation (last iteration, atomic-free) ----------------
__global__ void triplet_csr_kernel(const int* __restrict__ trip, const float* __restrict__ dist,
                                   const float* __restrict__ ang, const float* __restrict__ tab,
                                   const float* __restrict__ m_src, float* __restrict__ agg)
{
    int a = (blockIdx.x * blockDim.x + threadIdx.x) >> 5;
    int lane = threadIdx.x & 31;
    if (a >= NATOM) return;
    int b0 = g_csr_off[a], b1 = g_csr_off[a + 1];
    float4 acc = make_float4(0.f, 0.f, 0.f, 0.f);
#pragma unroll 2
    for (int idx = b0; idx < b1; idx++) {
        int gw = g_csr_edge[idx];
        int ji = trip[gw * 3 + 0];
        int kj = trip[gw * 3 + 1];
        float aw = ang[ji];
        float4 mv = ((const float4*)(m_src + (size_t)kj * HID))[lane];
        float4 rv = tab_lerp_t(tab, dist[kj], lane);
        acc.x += mv.x * rv.x * aw;
        acc.y += mv.y * rv.y * aw;
        acc.z += mv.z * rv.z * aw;
        acc.w += mv.w * rv.w * aw;
    }
    ((float4*)(agg + (size_t)a * HID))[lane] = acc;
}

// ---------------- CSR edge scatter (atomic-free) ----------------
__global__ void scatter_csr_kernel(const int* __restrict__ ei, const float* __restrict__ dist,
                                   const float* __restrict__ tab)
{
    int a = (blockIdx.x * blockDim.x + threadIdx.x) >> 5;
    int lane = threadIdx.x & 31;
    if (a >= NATOM) return;
    int b0 = g_csr_off[a], b1 = g_csr_off[a + 1];
    float4 acc = make_float4(0.f, 0.f, 0.f, 0.f);
#pragma unroll 2
    for (int idx = b0; idx < b1; idx++) {
        int e = g_csr_edge[idx];
        int s = ei[e];
        float4 hv = ((const float4*)(g_h + (size_t)s * HID))[lane];
        float4 wv = tab_lerp_t(tab, dist[e], lane);
        acc.x += hv.x * wv.x;
        acc.y += hv.y * wv.y;
        acc.z += hv.z * wv.z;
        acc.w += hv.w * wv.w;
    }
    ((float4*)(g_x + (size_t)a * HID))[lane] = acc;
}

// ---------------- host launcher ----------------
extern "C" void kernel_launch(void* const* d_in, const int* in_sizes, int n_in,
                              void* d_out, int out_size)
{
    const int*   Z        = (const int*)d_in[0];
    const int*   ei       = (const int*)d_in[1];
    const float* dist     = (const float*)d_in[2];
    const float* dirs     = (const float*)d_in[3];
    const int*   trip     = (const int*)d_in[4];
    const float* atom_emb = (const float*)d_in[5];
    const float* embed_w  = (const float*)d_in[6];
    const float* embed_b  = (const float*)d_in[7];
    const float* ib_rad_w1 = (const float*)d_in[8];
    const float* ib_rad_b1 = (const float*)d_in[9];
    const float* ib_rad_w2 = (const float*)d_in[10];
    const float* ib_rad_b2 = (const float*)d_in[11];
    const float* ib_sph_w  = (const float*)d_in[12];
    const float* ib_sph_b  = (const float*)d_in[13];
    const float* ib_upd_w1 = (const float*)d_in[14];
    const float* ib_upd_b1 = (const float*)d_in[15];
    const float* ib_upd_w2 = (const float*)d_in[16];
    const float* ib_upd_b2 = (const float*)d_in[17];
    const float* ib_out_w  = (const float*)d_in[18];
    const float* ib_out_b  = (const float*)d_in[19];
    const float* ob_rad_w1 = (const float*)d_in[20];
    const float* ob_rad_b1 = (const float*)d_in[21];
    const float* ob_rad_w2 = (const float*)d_in[22];
    const float* ob_rad_b2 = (const float*)d_in[23];
    const float* ob_dense_w = (const float*)d_in[24];
    const float* ob_dense_b = (const float*)d_in[25];
    const float* ob_out_w  = (const float*)d_in[26];
    const float* ob_out_b  = (const float*)d_in[27];
    float* out = (float*)d_out;

    float *p_agg, *p_m0, *p_m1, *p_tabs, *p_ang;
    __nv_bfloat16 *p_wbh, *p_wbl;
    int *p_cnt, *p_pos;
    cudaGetSymbolAddress((void**)&p_m0,   g_m);
    cudaGetSymbolAddress((void**)&p_m1,   g_m2);
    cudaGetSymbolAddress((void**)&p_agg,  g_agg);
    cudaGetSymbolAddress((void**)&p_tabs, g_tabs);
    cudaGetSymbolAddress((void**)&p_ang,  g_ang4);
    cudaGetSymbolAddress((void**)&p_wbh,  g_wbh);
    cudaGetSymbolAddress((void**)&p_wbl,  g_wbl);
    cudaGetSymbolAddress((void**)&p_cnt,  g_csr_cnt);
    cudaGetSymbolAddress((void**)&p_pos,  g_csr_pos);
    float* mBuf[2] = { p_m0, p_m1 };

    cudaFuncSetAttribute(rad_mlp_batch_kernel, cudaFuncAttributeMaxDynamicSharedMemorySize, RAD_SMEM);
    cudaFuncSetAttribute(fused_trip_mma_kernel<true >, cudaFuncAttributeMaxDynamicSharedMemorySize, FUSED_SMEM);
    cudaFuncSetAttribute(fused_trip_mma_kernel<false>, cudaFuncAttributeMaxDynamicSharedMemorySize, FUSED_SMEM);
    cudaFuncSetAttribute(hupdate_kernel, cudaFuncAttributeMaxDynamicSharedMemorySize, HUPD_SMEM);
    cudaFuncSetAttribute(outblock_kernel<false>, cudaFuncAttributeMaxDynamicSharedMemorySize, OUT_SMEM);
    cudaFuncSetAttribute(outblock_kernel<true >, cudaFuncAttributeMaxDynamicSharedMemorySize, OUT_SMEM);

    const int GT = NTAB / 64;             // 128
    const int GA = (NATOM + 63) / 64;     // 157
    const int GM = NEDGE / 128;           // 2500
    const int GC = (NATOM * 32 + 255) / 256;
    const size_t AGG_BYTES = (size_t)NATOM * HID * sizeof(float);
    const size_t TABSZ = (size_t)NTAB * HID;

    cudaStream_t sB;
    cudaStreamCreateWithFlags(&sB, cudaStreamNonBlocking);
    cudaEvent_t eTab, eTm, eCSR, eTabs, eF[4];
    cudaEventCreateWithFlags(&eTab, cudaEventDisableTiming);
    cudaEventCreateWithFlags(&eTm, cudaEventDisableTiming);
    cudaEventCreateWithFlags(&eCSR, cudaEventDisableTiming);
    cudaEventCreateWithFlags(&eTabs, cudaEventDisableTiming);
    for (int i = 0; i < 4; i++) cudaEventCreateWithFlags(&eF[i], cudaEventDisableTiming);

    // ---- A prologue: rbf table, CSR build, m table ----
    tab_prep_kernel<<<NTAB / 256, 256>>>();
    cudaEventRecord(eTab, 0);
    cudaMemsetAsync(p_cnt, 0, NATOM * sizeof(int));
    cudaMemsetAsync(p_pos, 0, NATOM * sizeof(int));
    csr_count_kernel<<<(NEDGE + 255) / 256, 256>>>(ei);
    csr_scan_kernel<<<1, 1024>>>();
    csr_fill_kernel<<<(NEDGE + 255) / 256, 256>>>(ei);
    cudaEventRecord(eCSR, 0);
    tabm_kernel<<<NTAB / 8, 256>>>(embed_w, embed_b);
    cudaEventRecord(eTm, 0);

    // ---- B prologue: angles, weights, h, all 9 radial tables ----
    {
        dim3 ga((NEDGE + 255) / 256, 4);
        angle_batch_kernel<<<ga, 256, 0, sB>>>(ib_sph_w, ib_sph_b, dirs);
    }
    cudaStreamWaitEvent(sB, eTab, 0);
    wsplit_kernel<<<(9 * HID * HID + 255) / 256, 256, 0, sB>>>(ib_out_w);
    h_init_kernel<<<(NATOM * 32 + 255) / 256, 256, 0, sB>>>(Z, atom_emb);
    {
        dim3 gr(GT, 9);
        rad_mlp_batch_kernel<<<gr, 256, RAD_SMEM, sB>>>(ob_rad_w1, ob_rad_b1, ob_rad_w2, ob_rad_b2,
                                                        ib_rad_w1, ib_rad_b1, ib_rad_w2, ib_rad_b2);
    }
    cudaEventRecord(eTabs, sB);

    // ---- B: zero agg buffers, free-running fused chain ----
    cudaMemsetAsync(p_agg, 0, 3 * AGG_BYTES, sB);
    cudaStreamWaitEvent(sB, eTm, 0);   // tabm ready for fused<true>
    fused_trip_mma_kernel<true><<<GM, 512, FUSED_SMEM, sB>>>(trip, ei, dist,
        p_ang, p_tabs + (size_t)5 * TABSZ,
        mBuf[0] /*unused*/, mBuf[1], p_agg,
        p_wbh, p_wbl, ib_out_b);
    cudaEventRecord(eF[0], sB);
    for (int i = 1; i < 3; i++) {
        fused_trip_mma_kernel<false><<<GM, 512, FUSED_SMEM, sB>>>(trip, ei, dist,
            p_ang + (size_t)i * NEDGE, p_tabs + (size_t)(5 + i) * TABSZ,
            mBuf[i & 1], mBuf[(i + 1) & 1], p_agg + (size_t)i * NATOM * HID,
            p_wbh + (size_t)i * 3 * 16384, p_wbl + (size_t)i * 3 * 16384,
            ib_out_b + i * 3 * 128);
        cudaEventRecord(eF[i], sB);
    }
    cudaStreamWaitEvent(sB, eCSR, 0);
    triplet_csr_kernel<<<GC, 256, 0, sB>>>(trip, dist, p_ang + (size_t)3 * NEDGE,
                                           p_tabs + (size_t)8 * TABSZ,
                                           mBuf[1], p_agg + (size_t)3 * NATOM * HID);
    cudaEventRecord(eF[3], sB);

    // ---- A: output block 0 (h + tables done at eTabs; CSR ordered on A) ----
    cudaStreamWaitEvent(0, eTabs, 0);
    scatter_csr_kernel<<<GC, 256>>>(ei, dist, p_tabs);
    outblock_kernel<false><<<GA, 256, OUT_SMEM>>>(ob_dense_w, ob_dense_b, ob_out_w, ob_out_b, out, NATOM);

    for (int i = 0; i < 4; i++) {
        cudaStreamWaitEvent(0, eF[i], 0);
        hupdate_kernel<<<GA, 256, HUPD_SMEM>>>(p_agg + (size_t)i * NATOM * HID,
                                               ib_upd_w1 + (size_t)i * 32768, ib_upd_b1 + i * 128,
                                               ib_upd_w2 + (size_t)i * 16384, ib_upd_b2 + i * 128, NATOM);
        int ob = i + 1;
        scatter_csr_kernel<<<GC, 256>>>(ei, dist, p_tabs + (size_t)ob * TABSZ);
        outblock_kernel<true><<<GA, 256, OUT_SMEM>>>(ob_dense_w + (size_t)ob * 3 * 16384,
                                                     ob_dense_b + ob * 3 * 128,
                                                     ob_out_w + ob * 128, ob_out_b + ob, out, NATOM);
    }
}